// round 2
// baseline (speedup 1.0000x reference)
#include <cuda_runtime.h>
#include <cstdint>

#define HD   128
#define TS   512
#define BSZ  4096
#define CD   10
#define BT   32
#define NCTA (BSZ / BT)   // 128
#define NTHR 256

// ---- shared memory layout (bytes) ----
#define SM_W 0                    // Whh transposed+swizzled [k][m] : 64 KB
#define SM_X (64 * 1024)          // xs[b][t]                      : 64 KB
#define SM_H (128 * 1024)         // h[2][b][k]                    : 32 KB
#define SM_F (160 * 1024)         // flags: sflags[2][8], absorb, xmax
#define SM_SZ (SM_F + 128)

typedef unsigned long long ull;

static __device__ __forceinline__ ull pk(float lo, float hi) {
    ull r;
    asm("mov.b64 %0, {%1, %2};" : "=l"(r) : "f"(lo), "f"(hi));
    return r;
}
static __device__ __forceinline__ void upk(ull v, float& lo, float& hi) {
    asm("mov.b64 {%0, %1}, %2;" : "=f"(lo), "=f"(hi) : "l"(v));
}
// packed fp32 FMA (FFMA2) — base sm_100-family PTX, not arch-'a' gated
static __device__ __forceinline__ ull fma2(ull a, ull b, ull c) {
    ull d;
    asm("fma.rn.f32x2 %0, %1, %2, %3;" : "=l"(d) : "l"(a), "l"(b), "l"(c));
    return d;
}
// accurate tanh: 1 - 2/(e^{2|x|}+1), odd-reflected. abs err ~1e-7 in the
// transition region; returns exactly +-1.0f for |x| >~ 8.7 (matches fp32
// tanhf/jnp.tanh saturation behavior).
static __device__ __forceinline__ float tanh_acc(float v) {
    float a = fabsf(v);
    float e = __expf(2.0f * a);          // inf for large a -> r = 1 exactly
    float r = 1.0f - 2.0f / (e + 1.0f);
    return copysignf(r, v);
}

// Whh element (m,k) lives at byte offset:
//   k*512 + (((m>>2) ^ (k&31)) << 4) + ((m&3) << 2)
// XOR chunk swizzle -> conflict-free LDS.128 in the mainloop (lane tm reads
// chunk tm ^ (k&31): a permutation of the 512B row).

__global__ void __launch_bounds__(NTHR, 1)
rnn_kernel(const float* __restrict__ x,   const float* __restrict__ Whx,
           const float* __restrict__ Whh, const float* __restrict__ Wph,
           const float* __restrict__ bh,  const float* __restrict__ bp,
           float* __restrict__ out)
{
    extern __shared__ char sm[];
    float* Xs = (float*)(sm + SM_X);
    float* Hs = (float*)(sm + SM_H);                    // [2][32][128]
    int*   sflags = (int*)(sm + SM_F);                  // [2][8]
    int*   absorb = (int*)(sm + SM_F + 64);
    unsigned* xmaxb = (unsigned*)(sm + SM_F + 68);

    const int tid  = threadIdx.x;
    const int lane = tid & 31;          // m-tile: m = 4*lane .. 4*lane+3
    const int wid  = tid >> 5;          // b-tile: b = 4*wid  .. 4*wid+3
    const int b0   = blockIdx.x * BT;

    if (tid == 0) { *absorb = 1; *xmaxb = 0u; }

    // __syncthreads not needed before writes below; atomics happen after full
    // preload, and absorb/xmax are only read after the next barrier.
    __syncthreads();

    // ---- Whh load (coalesced LDG) -> transposed+swizzled smem ----
    for (int i = tid; i < HD * HD; i += NTHR) {
        int m = i >> 7, k = i & 127;                       // consecutive k per lane
        float v = Whh[i];
        uint32_t off = (uint32_t)k * 512u
                     + ((uint32_t)(((m >> 2) ^ (k & 31))) << 4)
                     + ((uint32_t)(m & 3) << 2);
        *(float*)(sm + SM_W + off) = v;
    }
    // ---- x preload: xs[b][t], track max|x| ----
    float lm = 0.0f;
    for (int i = tid; i < BT * TS; i += NTHR) {
        int b = i >> 9, t = i & 511;
        float v = x[(size_t)(b0 + b) * TS + t];
        Xs[(b << 9) + t] = v;
        lm = fmaxf(lm, fabsf(v));
    }
    atomicMax(xmaxb, __float_as_uint(lm));                 // |x| bits are order-preserving
    // ---- h0 = 0 ----
    for (int i = tid; i < BT * HD; i += NTHR) Hs[i] = 0.0f;
    __syncthreads();

    // ---- absorption certificate: min_m (rowsum_m - |Whx_m|*Xmax - |bh_m|) > 10 ----
    if (tid < HD) {
        int m = tid;
        float rs = 0.0f;
        for (int k = 0; k < HD; ++k) {
            uint32_t off = (uint32_t)k * 512u
                         + ((uint32_t)(((m >> 2) ^ (k & 31))) << 4)
                         + ((uint32_t)(m & 3) << 2);
            rs += *(const float*)(sm + SM_W + off);
        }
        float xmf = __uint_as_float(*xmaxb);
        float bound = rs - fabsf(Whx[m]) * xmf - fabsf(bh[m]);
        if (!(bound > 10.0f)) atomicAnd(absorb, 0);
    }
    __syncthreads();
    const bool absorb_ok = (*absorb != 0);

    // ---- per-thread constants (m = 4*lane..+3) ----
    const float4 wxv = *(const float4*)(Whx + 4 * lane);
    const float4 bhv = *(const float4*)(bh  + 4 * lane);
    const ull wx01 = pk(wxv.x, wxv.y), wx23 = pk(wxv.z, wxv.w);
    const ull bh01 = pk(bhv.x, bhv.y), bh23 = pk(bhv.z, bhv.w);

    // ================= main recurrence =================
    int cur = 0;
    for (int t = 0; t < TS; ++t) {
        const float* hrd = Hs + cur * (BT * HD);
        float*       hwr = Hs + (cur ^ 1) * (BT * HD);

        ull acc[4][2];
        #pragma unroll
        for (int j = 0; j < 4; ++j) {
            float xv = Xs[((4 * wid + j) << 9) + t];
            ull xp = pk(xv, xv);
            acc[j][0] = fma2(wx01, xp, bh01);
            acc[j][1] = fma2(wx23, xp, bh23);
        }

        #pragma unroll 2
        for (int k4 = 0; k4 < 32; ++k4) {
            float4 hv[4];
            #pragma unroll
            for (int j = 0; j < 4; ++j)                      // uniform -> broadcast
                hv[j] = *(const float4*)(hrd + ((4 * wid + j) << 7) + (k4 << 2));
            #pragma unroll
            for (int jj = 0; jj < 4; ++jj) {
                int k = k4 * 4 + jj;
                uint32_t off = (uint32_t)k * 512u
                             + ((uint32_t)((lane ^ (k & 31))) << 4);
                float4 w4 = *(const float4*)(sm + SM_W + off);   // conflict-free LDS.128
                ull wp0 = pk(w4.x, w4.y), wp1 = pk(w4.z, w4.w);
                #pragma unroll
                for (int j = 0; j < 4; ++j) {
                    float hx = (jj == 0) ? hv[j].x : (jj == 1) ? hv[j].y
                             : (jj == 2) ? hv[j].z : hv[j].w;
                    ull rp = pk(hx, hx);
                    acc[j][0] = fma2(wp0, rp, acc[j][0]);
                    acc[j][1] = fma2(wp1, rp, acc[j][1]);
                }
            }
        }

        // ---- epilogue: tanh, saturation vote, write-back ----
        int warp_ok = 1;
        #pragma unroll
        for (int j = 0; j < 4; ++j) {
            float v0, v1, v2, v3;
            upk(acc[j][0], v0, v1);
            upk(acc[j][1], v2, v3);
            v0 = tanh_acc(v0); v1 = tanh_acc(v1);
            v2 = tanh_acc(v2); v3 = tanh_acc(v3);
            bool allp = (v0 ==  1.0f) & (v1 ==  1.0f) & (v2 ==  1.0f) & (v3 ==  1.0f);
            bool alln = (v0 == -1.0f) & (v1 == -1.0f) & (v2 == -1.0f) & (v3 == -1.0f);
            unsigned bp_ = __ballot_sync(0xffffffffu, allp);
            unsigned bn_ = __ballot_sync(0xffffffffu, alln);
            warp_ok &= (int)((bp_ == 0xffffffffu) | (bn_ == 0xffffffffu));
            float4 o4 = make_float4(v0, v1, v2, v3);
            *(float4*)(hwr + ((4 * wid + j) << 7) + 4 * lane) = o4;  // contiguous STS.128
        }
        if (lane == 0) sflags[(t & 1) * 8 + wid] = warp_ok;   // parity-buffered flags
        __syncthreads();
        cur ^= 1;
        if (absorb_ok) {
            int done = 1;
            #pragma unroll
            for (int w = 0; w < 8; ++w) done &= sflags[(t & 1) * 8 + w];
            if (done) break;     // uniform: all threads read the same epoch's flags
        }
    }

    // ================= projection: out[b,c] = Wph[c,:] @ h[:,b] + bp[c] =================
    const float* hf = Hs + cur * (BT * HD);
    for (int idx = tid; idx < BT * CD; idx += NTHR) {
        int b = idx / CD, c = idx - b * CD;
        float s = bp[c];
        #pragma unroll 8
        for (int m = 0; m < HD; ++m)
            s = fmaf(__ldg(Wph + c * HD + m), hf[(b << 7) + m], s);
        out[(size_t)(b0 + b) * CD + c] = s;
    }
}

extern "C" void kernel_launch(void* const* d_in, const int* in_sizes, int n_in,
                              void* d_out, int out_size) {
    const float* x   = (const float*)d_in[0];
    const float* Whx = (const float*)d_in[1];
    const float* Whh = (const float*)d_in[2];
    const float* Wph = (const float*)d_in[3];
    const float* bh  = (const float*)d_in[4];
    const float* bp  = (const float*)d_in[5];
    cudaFuncSetAttribute(rnn_kernel, cudaFuncAttributeMaxDynamicSharedMemorySize, SM_SZ);
    rnn_kernel<<<NCTA, NTHR, SM_SZ>>>(x, Whx, Whh, Wph, bh, bp, (float*)d_out);
}

// round 3
// speedup vs baseline: 1.7602x; 1.7602x over previous
#include <cuda_runtime.h>
#include <cstdint>

#define HD   128
#define TS   512
#define BSZ  4096
#define CD   10
#define BT   32
#define NCTA (BSZ / BT)   // 128
#define NTHR 256
#define TPREF 128         // timesteps of x kept in smem

// ---- shared memory layout (bytes) ----
#define SM_W 0                       // Whh^T swizzled [k][m]      : 64 KB
#define SM_X (64 * 1024)             // xs[32][TPREF]              : 16 KB
#define SM_H (80 * 1024)             // h[32][128] (in-place)      : 16 KB
#define SM_P (96 * 1024)             // Wph [10][128]              : 5 KB
#define SM_F (101 * 1024 + 256)      // absorb flag, xmax
#define SM_SZ (SM_F + 128)

typedef unsigned long long ull;

static __device__ __forceinline__ ull pk(float lo, float hi) {
    ull r; asm("mov.b64 %0, {%1, %2};" : "=l"(r) : "f"(lo), "f"(hi)); return r;
}
static __device__ __forceinline__ void upk(ull v, float& lo, float& hi) {
    asm("mov.b64 {%0, %1}, %2;" : "=f"(lo), "=f"(hi) : "l"(v));
}
static __device__ __forceinline__ ull fma2(ull a, ull b, ull c) {
    ull d; asm("fma.rn.f32x2 %0, %1, %2, %3;" : "=l"(d) : "l"(a), "l"(b), "l"(c)); return d;
}
// accurate tanh: exactly +-1.0f for |x| >~ 9 (matches fp32 tanhf saturation)
static __device__ __forceinline__ float tanh_acc(float v) {
    float a = fabsf(v);
    float e = __expf(2.0f * a);
    float r = 1.0f - 2.0f / (e + 1.0f);
    return copysignf(r, v);
}

// Whh element (m,k) at byte offset: k*512 + (((m>>2)^(k&31))<<4) + ((m&3)<<2)
// -> lane reads its m-quad with chunk index lane^(k&31): conflict-free LDS.128.

// One recurrence step for J active columns owned by this warp. In-place h.
// Returns bitmask of columns that just absorbed (uniform across the warp).
template <int J>
static __device__ __forceinline__ unsigned
do_step(char* sm, int lane, const int* cols, const float* xv,
        ull wx01, ull wx23, ull bh01, ull bh23)
{
    float* Hs = (float*)(sm + SM_H);
    ull acc[J][2];
    #pragma unroll
    for (int j = 0; j < J; ++j) {
        ull xp = pk(xv[j], xv[j]);
        acc[j][0] = fma2(wx01, xp, bh01);
        acc[j][1] = fma2(wx23, xp, bh23);
    }
    #pragma unroll 4
    for (int k4 = 0; k4 < 32; ++k4) {
        float4 hv[J];
        #pragma unroll
        for (int j = 0; j < J; ++j)
            hv[j] = *(const float4*)(Hs + cols[j] * HD + k4 * 4);   // broadcast
        #pragma unroll
        for (int jj = 0; jj < 4; ++jj) {
            int k = k4 * 4 + jj;
            const float4 w4 = *(const float4*)(sm + SM_W + k * 512
                                               + ((lane ^ (k & 31)) << 4));
            ull wp0 = pk(w4.x, w4.y), wp1 = pk(w4.z, w4.w);
            #pragma unroll
            for (int j = 0; j < J; ++j) {
                float hx = (jj == 0) ? hv[j].x : (jj == 1) ? hv[j].y
                         : (jj == 2) ? hv[j].z : hv[j].w;
                ull rp = pk(hx, hx);
                acc[j][0] = fma2(wp0, rp, acc[j][0]);
                acc[j][1] = fma2(wp1, rp, acc[j][1]);
            }
        }
    }
    unsigned am = 0;
    #pragma unroll
    for (int j = 0; j < J; ++j) {
        float v0, v1, v2, v3;
        upk(acc[j][0], v0, v1); upk(acc[j][1], v2, v3);
        v0 = tanh_acc(v0); v1 = tanh_acc(v1);
        v2 = tanh_acc(v2); v3 = tanh_acc(v3);
        // in-place write: this warp is the sole reader/writer of its columns,
        // and all k-loop reads precede these stores in program order.
        *(float4*)(Hs + cols[j] * HD + 4 * lane) = make_float4(v0, v1, v2, v3);
        bool allp = (v0 ==  1.0f) & (v1 ==  1.0f) & (v2 ==  1.0f) & (v3 ==  1.0f);
        bool alln = (v0 == -1.0f) & (v1 == -1.0f) & (v2 == -1.0f) & (v3 == -1.0f);
        unsigned bp_ = __ballot_sync(0xffffffffu, allp);
        unsigned bn_ = __ballot_sync(0xffffffffu, alln);
        if ((bp_ == 0xffffffffu) | (bn_ == 0xffffffffu)) am |= 1u << j;
    }
    return am;
}

__global__ void __launch_bounds__(NTHR, 1)
rnn_kernel(const float* __restrict__ x,   const float* __restrict__ Whx,
           const float* __restrict__ Whh, const float* __restrict__ Wph,
           const float* __restrict__ bh,  const float* __restrict__ bp,
           float* __restrict__ out)
{
    extern __shared__ char sm[];
    float* Xs   = (float*)(sm + SM_X);
    float* Hs   = (float*)(sm + SM_H);
    float* WphS = (float*)(sm + SM_P);
    int*      absorb = (int*)(sm + SM_F);
    unsigned* xmaxb  = (unsigned*)(sm + SM_F + 4);

    const int tid  = threadIdx.x;
    const int lane = tid & 31;          // m-quad: m = 4*lane..4*lane+3
    const int wid  = tid >> 5;          // owns columns 4*wid..4*wid+3
    const int b0   = blockIdx.x * BT;

    if (tid == 0) { *absorb = 1; *xmaxb = 0u; }
    __syncthreads();

    // ---- Whh -> transposed+swizzled smem (float4 LDG, scalar swizzled STS) ----
    {
        const float4* W4 = (const float4*)Whh;
        for (int i = tid; i < HD * HD / 4; i += NTHR) {
            float4 v = W4[i];
            int m = i >> 5, k = (i & 31) * 4;
            float vv[4] = {v.x, v.y, v.z, v.w};
            #pragma unroll
            for (int q = 0; q < 4; ++q) {
                int kk = k + q;
                uint32_t off = (uint32_t)kk * 512u
                             + ((uint32_t)(((m >> 2) ^ (kk & 31))) << 4)
                             + ((uint32_t)(m & 3) << 2);
                *(float*)(sm + SM_W + off) = vv[q];
            }
        }
    }
    // ---- x: streaming max over all 512 t; store only t < TPREF ----
    {
        float lm = 0.0f;
        for (int i = tid; i < BT * TS / 4; i += NTHR) {
            int b = i >> 7, tq = i & 127;                 // t = 4*tq
            float4 v = *(const float4*)(x + (size_t)(b0 + b) * TS + 4 * tq);
            lm = fmaxf(lm, fmaxf(fmaxf(fabsf(v.x), fabsf(v.y)),
                                 fmaxf(fabsf(v.z), fabsf(v.w))));
            if (tq < TPREF / 4)
                *(float4*)(Xs + b * TPREF + 4 * tq) = v;
        }
        atomicMax(xmaxb, __float_as_uint(lm));            // |x| bits order-preserving
    }
    // ---- h0 = 0, Wph preload ----
    for (int i = tid; i < BT * HD / 4; i += NTHR)
        *(float4*)(Hs + 4 * i) = make_float4(0.f, 0.f, 0.f, 0.f);
    for (int i = tid; i < CD * HD / 4; i += NTHR)
        ((float4*)WphS)[i] = ((const float4*)Wph)[i];
    __syncthreads();

    // ---- absorption certificate: min_m (rowsum_m - |Whx_m|*Xmax - |bh_m|) > 10 ----
    if (tid < HD) {
        int m = tid;
        float rs = 0.0f;
        for (int k = 0; k < HD; ++k) {
            uint32_t off = (uint32_t)k * 512u
                         + ((uint32_t)(((m >> 2) ^ (k & 31))) << 4)
                         + ((uint32_t)(m & 3) << 2);
            rs += *(const float*)(sm + SM_W + off);
        }
        float bound = rs - fabsf(Whx[m]) * __uint_as_float(*xmaxb) - fabsf(bh[m]);
        if (!(bound > 10.0f)) atomicAnd(absorb, 0);
    }
    __syncthreads();
    const bool absorb_ok = (*absorb != 0);

    // ---- per-thread constants ----
    const float4 wxv = *(const float4*)(Whx + 4 * lane);
    const float4 bhv = *(const float4*)(bh  + 4 * lane);
    const ull wx01 = pk(wxv.x, wxv.y), wx23 = pk(wxv.z, wxv.w);
    const ull bh01 = pk(bhv.x, bhv.y), bh23 = pk(bhv.z, bhv.w);

    // ================= barrier-free per-warp recurrence =================
    int cols[4] = {4 * wid, 4 * wid + 1, 4 * wid + 2, 4 * wid + 3};
    int nact = 4;

    for (int t = 0; t < TS && nact > 0; ++t) {
        float xv[4] = {0.f, 0.f, 0.f, 0.f};
        #pragma unroll
        for (int j = 0; j < 4; ++j)
            if (j < nact)
                xv[j] = (t < TPREF) ? Xs[cols[j] * TPREF + t]
                                    : __ldg(x + (size_t)(b0 + cols[j]) * TS + t);
        unsigned am = 0;
        switch (nact) {
            case 4: am = do_step<4>(sm, lane, cols, xv, wx01, wx23, bh01, bh23); break;
            case 3: am = do_step<3>(sm, lane, cols, xv, wx01, wx23, bh01, bh23); break;
            case 2: am = do_step<2>(sm, lane, cols, xv, wx01, wx23, bh01, bh23); break;
            default: am = do_step<1>(sm, lane, cols, xv, wx01, wx23, bh01, bh23); break;
        }
        if (absorb_ok && am) {        // warp-local compaction (uniform values)
            int nn = 0, nc[4];
            #pragma unroll
            for (int j = 0; j < 4; ++j)
                if (j < nact && !((am >> j) & 1u)) nc[nn++] = cols[j];
            nact = nn;
            #pragma unroll
            for (int j = 0; j < 4; ++j) cols[j] = (j < nn) ? nc[j] : 0;
        }
    }

    // ================= per-warp projection of its 4 columns =================
    #pragma unroll
    for (int j = 0; j < 4; ++j) {
        int c = 4 * wid + j;
        const float4 hq = *(const float4*)(Hs + c * HD + 4 * lane);
        float s[CD];
        #pragma unroll
        for (int cls = 0; cls < CD; ++cls) {
            const float4 wq = *(const float4*)(WphS + cls * HD + 4 * lane);
            s[cls] = hq.x * wq.x + hq.y * wq.y + hq.z * wq.z + hq.w * wq.w;
        }
        #pragma unroll
        for (int cls = 0; cls < CD; ++cls) {
            float v = s[cls];
            v += __shfl_xor_sync(0xffffffffu, v, 16);
            v += __shfl_xor_sync(0xffffffffu, v, 8);
            v += __shfl_xor_sync(0xffffffffu, v, 4);
            v += __shfl_xor_sync(0xffffffffu, v, 2);
            v += __shfl_xor_sync(0xffffffffu, v, 1);
            if (lane == 0)
                out[(size_t)(b0 + c) * CD + cls] = v + __ldg(bp + cls);
        }
    }
}

extern "C" void kernel_launch(void* const* d_in, const int* in_sizes, int n_in,
                              void* d_out, int out_size) {
    const float* x   = (const float*)d_in[0];
    const float* Whx = (const float*)d_in[1];
    const float* Whh = (const float*)d_in[2];
    const float* Wph = (const float*)d_in[3];
    const float* bh  = (const float*)d_in[4];
    const float* bp  = (const float*)d_in[5];
    cudaFuncSetAttribute(rnn_kernel, cudaFuncAttributeMaxDynamicSharedMemorySize, SM_SZ);
    rnn_kernel<<<NCTA, NTHR, SM_SZ>>>(x, Whx, Whh, Wph, bh, bp, (float*)d_out);
}

// round 4
// speedup vs baseline: 2.4089x; 1.3686x over previous
#include <cuda_runtime.h>
#include <cstdint>

#define HD   128
#define TS   512
#define BSZ  4096
#define CD   10
#define BT   32
#define NCTA (BSZ / BT)   // 128
#define NTHR 512
#define TPREF 128

// ---- shared memory layout (bytes) ----
#define SM_W 0                       // Whh^T  Ws[k][m]            : 64 KB
#define SM_X (64 * 1024)             // xs[32][TPREF]              : 16 KB
#define SM_H (80 * 1024)             // h[2][32][128] ping-pong    : 32 KB
#define SM_F (112 * 1024)            // flags[2][8][2], absorb, xmax
#define SM_SZ (SM_F + 256)

typedef unsigned long long ull;

static __device__ __forceinline__ ull pk(float lo, float hi) {
    ull r; asm("mov.b64 %0, {%1, %2};" : "=l"(r) : "f"(lo), "f"(hi)); return r;
}
static __device__ __forceinline__ void upk(ull v, float& lo, float& hi) {
    asm("mov.b64 {%0, %1}, %2;" : "=f"(lo), "=f"(hi) : "l"(v));
}
static __device__ __forceinline__ ull fma2(ull a, ull b, ull c) {
    ull d; asm("fma.rn.f32x2 %0, %1, %2, %3;" : "=l"(d) : "l"(a), "l"(b), "l"(c)); return d;
}
// exactly +-1.0f for |x| >~ 9 (matches fp32 tanhf saturation); ~1e-7 abs err
static __device__ __forceinline__ float tanh_acc(float v) {
    float a = fabsf(v);
    float e = __expf(2.0f * a);
    float r = 1.0f - 2.0f / (e + 1.0f);
    return copysignf(r, v);
}

// epilogue: tanh, write float2 to hwr, per-half-column uniform +-1 vote.
// returns am: bits[j]=half-all-+1, bits[8+j]=half-all--1 (uniform across warp)
template <int J>
static __device__ __forceinline__ unsigned
epilogue(const ull* acc, float* hwr, const int* cols, int mb)
{
    unsigned am = 0;
    #pragma unroll
    for (int j = 0; j < J; ++j) {
        float v0, v1; upk(acc[j], v0, v1);
        v0 = tanh_acc(v0); v1 = tanh_acc(v1);
        *(float2*)(hwr + cols[j] * HD + mb) = make_float2(v0, v1);
        bool p = (v0 ==  1.0f) & (v1 ==  1.0f);
        bool n = (v0 == -1.0f) & (v1 == -1.0f);
        unsigned bp_ = __ballot_sync(0xffffffffu, p);
        unsigned bn_ = __ballot_sync(0xffffffffu, n);
        if (bp_ == 0xffffffffu) am |= 1u << j;
        if (bn_ == 0xffffffffu) am |= 1u << (j + 8);
    }
    return am;
}

// one recurrence step for J live columns; this warp covers m = mb, mb+1.
template <int J>
static __device__ __forceinline__ unsigned
do_step(const char* sm, const int* cols, const float* xv, ull wx2, ull bh2,
        const float* hrd, float* hwr, int mb)
{
    ull acc[J];
    #pragma unroll
    for (int j = 0; j < J; ++j)
        acc[j] = fma2(wx2, pk(xv[j], xv[j]), bh2);
    #pragma unroll 4
    for (int k4 = 0; k4 < 32; ++k4) {
        float4 hv[J];
        #pragma unroll
        for (int j = 0; j < J; ++j)                       // broadcast LDS.128
            hv[j] = *(const float4*)(hrd + cols[j] * HD + k4 * 4);
        #pragma unroll
        for (int jj = 0; jj < 4; ++jj) {
            int k = 4 * k4 + jj;
            const float2 w2 = *(const float2*)(sm + SM_W + k * 512 + mb * 4);
            ull wp = pk(w2.x, w2.y);
            #pragma unroll
            for (int j = 0; j < J; ++j) {
                float hx = (jj == 0) ? hv[j].x : (jj == 1) ? hv[j].y
                         : (jj == 2) ? hv[j].z : hv[j].w;
                acc[j] = fma2(wp, pk(hx, hx), acc[j]);
            }
        }
    }
    return epilogue<J>(acc, hwr, cols, mb);
}

__global__ void __launch_bounds__(NTHR, 1)
rnn_kernel(const float* __restrict__ x,   const float* __restrict__ Whx,
           const float* __restrict__ Whh, const float* __restrict__ Wph,
           const float* __restrict__ bh,  const float* __restrict__ bp,
           float* __restrict__ out)
{
    extern __shared__ char sm[];
    float* Xs  = (float*)(sm + SM_X);
    float* Hb0 = (float*)(sm + SM_H);
    float* Hb1 = Hb0 + BT * HD;
    unsigned* sflag  = (unsigned*)(sm + SM_F);           // [2][8][2]
    int*      absorb = (int*)(sm + SM_F + 128);
    unsigned* xmaxb  = (unsigned*)(sm + SM_F + 132);

    const int tid  = threadIdx.x;
    const int lane = tid & 31;
    const int wid  = tid >> 5;
    const int pair = wid >> 1;                 // 0..7: owns cols 4*pair..+3
    const int half = wid & 1;                  // m half
    const int mb   = half * 64 + 2 * lane;     // this thread's m pair
    const int b0   = blockIdx.x * BT;

    if (tid == 0) { *absorb = 1; *xmaxb = 0u; }
    __syncthreads();

    // ---- Whh -> Ws[k][m] (lanes span m => conflict-free scalar STS) ----
    for (int i = tid; i < HD * HD / 4; i += NTHR) {
        int m = i & 127, kq = i >> 7;
        float4 v = *(const float4*)(Whh + (size_t)m * HD + 4 * kq);
        float vv[4] = {v.x, v.y, v.z, v.w};
        #pragma unroll
        for (int q = 0; q < 4; ++q)
            *(float*)(sm + SM_W + (4 * kq + q) * 512 + m * 4) = vv[q];
    }
    // ---- x: streaming max over all t; store t < TPREF ----
    {
        float lm = 0.0f;
        for (int i = tid; i < BT * TS / 4; i += NTHR) {
            int b = i >> 7, tq = i & 127;
            float4 v = *(const float4*)(x + (size_t)(b0 + b) * TS + 4 * tq);
            lm = fmaxf(lm, fmaxf(fmaxf(fabsf(v.x), fabsf(v.y)),
                                 fmaxf(fabsf(v.z), fabsf(v.w))));
            if (tq < TPREF / 4)
                *(float4*)(Xs + b * TPREF + 4 * tq) = v;
        }
        atomicMax(xmaxb, __float_as_uint(lm));
    }
    __syncthreads();

    // ---- absorption certificate: min_m(rowsum - |Whx|*Xmax - |bh|) > 10 ----
    if (tid < HD) {
        int m = tid;
        float s0 = 0.f, s1 = 0.f, s2 = 0.f, s3 = 0.f;
        for (int k = 0; k < HD; k += 4) {
            s0 += *(const float*)(sm + SM_W + (k    ) * 512 + m * 4);
            s1 += *(const float*)(sm + SM_W + (k + 1) * 512 + m * 4);
            s2 += *(const float*)(sm + SM_W + (k + 2) * 512 + m * 4);
            s3 += *(const float*)(sm + SM_W + (k + 3) * 512 + m * 4);
        }
        float rs = (s0 + s1) + (s2 + s3);
        float bound = rs - fabsf(Whx[m]) * __uint_as_float(*xmaxb) - fabsf(bh[m]);
        if (!(bound > 10.0f)) atomicAnd(absorb, 0);
    }
    __syncthreads();
    const bool absorb_ok = (*absorb != 0);

    const float2 wxv = *(const float2*)(Whx + mb);
    const float2 bhv = *(const float2*)(bh  + mb);
    const ull wx2 = pk(wxv.x, wxv.y);
    const ull bh2 = pk(bhv.x, bhv.y);

    // ================= per-pair recurrence (named-barrier scoped) =================
    int cols[4] = {4 * pair, 4 * pair + 1, 4 * pair + 2, 4 * pair + 3};
    int nact = 4, cur = 0;

    for (int t = 0; t < TS && nact > 0; ++t) {
        const float* hrd = (cur == 0) ? Hb0 : Hb1;
        float*       hwr = (cur == 0) ? Hb1 : Hb0;

        float xv[4] = {0.f, 0.f, 0.f, 0.f};
        #pragma unroll
        for (int j = 0; j < 4; ++j)
            if (j < nact)
                xv[j] = (t < TPREF) ? Xs[cols[j] * TPREF + t]
                                    : __ldg(x + (size_t)(b0 + cols[j]) * TS + t);
        unsigned am;
        if (t == 0) {
            // h0 = 0: skip the GEMV entirely; h1 = tanh(Whx*x0 + bh)
            ull acc[4];
            #pragma unroll
            for (int j = 0; j < 4; ++j)
                acc[j] = fma2(wx2, pk(xv[j], xv[j]), bh2);
            am = epilogue<4>(acc, hwr, cols, mb);
        } else switch (nact) {
            case 4: am = do_step<4>(sm, cols, xv, wx2, bh2, hrd, hwr, mb); break;
            case 3: am = do_step<3>(sm, cols, xv, wx2, bh2, hrd, hwr, mb); break;
            case 2: am = do_step<2>(sm, cols, xv, wx2, bh2, hrd, hwr, mb); break;
            default: am = do_step<1>(sm, cols, xv, wx2, bh2, hrd, hwr, mb); break;
        }

        if (lane == 0) sflag[(t & 1) * 16 + pair * 2 + half] = am;
        asm volatile("bar.sync %0, 64;" :: "r"(1 + pair) : "memory");
        unsigned f0 = sflag[(t & 1) * 16 + pair * 2 + 0];
        unsigned f1 = sflag[(t & 1) * 16 + pair * 2 + 1];
        cur ^= 1;

        if (absorb_ok) {
            unsigned amp = f0 & f1 & 0xFu;
            unsigned amn = (f0 >> 8) & (f1 >> 8) & 0xFu;
            unsigned ab  = (amp | amn) & ((1u << nact) - 1u);
            if (ab) {
                // absorbed columns are uniform +-1: materialize in BOTH buffers
                #pragma unroll
                for (int j = 0; j < 4; ++j)
                    if (j < nact && ((ab >> j) & 1u)) {
                        float s = ((amp >> j) & 1u) ? 1.0f : -1.0f;
                        float2 sv = make_float2(s, s);
                        *(float2*)(Hb0 + cols[j] * HD + mb) = sv;
                        *(float2*)(Hb1 + cols[j] * HD + mb) = sv;
                    }
                int nn = 0, nc[4];
                #pragma unroll
                for (int j = 0; j < 4; ++j)
                    if (j < nact && !((ab >> j) & 1u)) nc[nn++] = cols[j];
                nact = nn;
                #pragma unroll
                for (int j = 0; j < 4; ++j) cols[j] = (j < nn) ? nc[j] : 0;
            }
        }
    }
    // make pair-mate's post-barrier sign-writes visible before projection
    asm volatile("bar.sync %0, 64;" :: "r"(1 + pair) : "memory");

    // ================= projection: warp handles 2 of its pair's columns =================
    const float* hf = (cur == 0) ? Hb0 : Hb1;
    {
        int c0 = 4 * pair + 2 * half, c1 = c0 + 1;
        const float4 h0q = *(const float4*)(hf + c0 * HD + 4 * lane);
        const float4 h1q = *(const float4*)(hf + c1 * HD + 4 * lane);
        #pragma unroll
        for (int cls = 0; cls < CD; ++cls) {
            const float4 wq = __ldg((const float4*)(Wph + cls * HD) + lane);
            float s0 = h0q.x * wq.x + h0q.y * wq.y + h0q.z * wq.z + h0q.w * wq.w;
            float s1 = h1q.x * wq.x + h1q.y * wq.y + h1q.z * wq.z + h1q.w * wq.w;
            #pragma unroll
            for (int o = 16; o > 0; o >>= 1) {
                s0 += __shfl_xor_sync(0xffffffffu, s0, o);
                s1 += __shfl_xor_sync(0xffffffffu, s1, o);
            }
            if (lane == 0) {
                float bpv = __ldg(bp + cls);
                out[(size_t)(b0 + c0) * CD + cls] = s0 + bpv;
                out[(size_t)(b0 + c1) * CD + cls] = s1 + bpv;
            }
        }
    }
}

extern "C" void kernel_launch(void* const* d_in, const int* in_sizes, int n_in,
                              void* d_out, int out_size) {
    const float* x   = (const float*)d_in[0];
    const float* Whx = (const float*)d_in[1];
    const float* Whh = (const float*)d_in[2];
    const float* Wph = (const float*)d_in[3];
    const float* bh  = (const float*)d_in[4];
    const float* bp  = (const float*)d_in[5];
    cudaFuncSetAttribute(rnn_kernel, cudaFuncAttributeMaxDynamicSharedMemorySize, SM_SZ);
    rnn_kernel<<<NCTA, NTHR, SM_SZ>>>(x, Whx, Whh, Wph, bh, bp, (float*)d_out);
}